// round 10
// baseline (speedup 1.0000x reference)
#include <cuda_runtime.h>

#define BB 4
#define NN 16384
#define CC 64
#define KI 16
#define HH 8

// ---------------- fused kernel: q-projection + gather + factored attention ----------------
// warp per point; lane = 4*g + kq; lane holds nb[c=8g..8g+7][kk=4kq..4kq+3]
__global__ __launch_bounds__(256, 2) void attn_kernel(
    const float* __restrict__ pcd, const float* __restrict__ neighbors,
    const float* __restrict__ xyz,
    const float* __restrict__ Wq, const float* __restrict__ Wk,
    const float* __restrict__ Wv,
    const int* __restrict__ idx_all, float* __restrict__ out)
{
    extern __shared__ float sm[];
    float* WkT_s = sm;                    // [c][o], 67*68
    float* WvT_s = WkT_s + 67 * 68;       // [c][o] transposed, 67*68
    float* Wq_s  = WvT_s + 67 * 68;       // [o][c] row-major, 64*68
    float* qhW_s = Wq_s + 64 * 68;        // [pt][h*68 + c], 8*544
    float* q_s   = qhW_s + 8 * 544;       // [pt][o], 512
    float* out_s = q_s + 512;             // [pt][o], 512
    float* pcd_s = out_s + 512;           // [nn][c] transposed, 8*68

    int t = threadIdx.x;
    for (int idx = t; idx < 64 * 67; idx += 256) {
        int o = idx / 67, c = idx % 67;
        WkT_s[c * 68 + o] = Wk[idx];
        WvT_s[c * 68 + o] = Wv[idx];
        Wq_s[o * 68 + c] = Wq[idx];
    }
    __syncthreads();

    const int pt = t >> 5, ln = t & 31, g = ln >> 2, kq = ln & 3;
    const int b0l = ln & 1, b1l = (ln >> 1) & 1, b2l = (ln >> 2) & 1;
    const int qo = t & 63, qp2 = t >> 6;          // q-projection mapping
    const int NTILE = (BB * NN) / 8;              // 8192

    for (int tile = blockIdx.x; tile < NTILE; tile += gridDim.x) {
        int b = (tile * 8) >> 14;
        int n0 = (tile * 8) & (NN - 1);

        // stage pcd_cat tile transposed: pcd_s[nn*68 + c]
        for (int idx = t; idx < 536; idx += 256) {
            int c = idx >> 3, nn = idx & 7;
            float v = (c < 64) ? pcd[(b * 64 + c) * NN + n0 + nn]
                               : xyz[(b * 3 + (c - 64)) * NN + n0 + nn];
            pcd_s[nn * 68 + c] = v;
        }
        __syncthreads();

        // q[pt][o] = sum_c Wq[o,c] * pcd_cat[c, n0+pt]; each thread does 2 pts
        {
            float a0 = 0.f, a1 = 0.f;
            const float* wr = Wq_s + qo * 68;
            const float* p0 = pcd_s + (2 * qp2) * 68;
            const float* p1 = p0 + 68;
            #pragma unroll
            for (int k4 = 0; k4 < 16; k4++) {
                float4 w = *(const float4*)(wr + 4 * k4);
                float4 x0 = *(const float4*)(p0 + 4 * k4);
                float4 x1 = *(const float4*)(p1 + 4 * k4);
                a0 += w.x * x0.x + w.y * x0.y + w.z * x0.z + w.w * x0.w;
                a1 += w.x * x1.x + w.y * x1.y + w.z * x1.z + w.w * x1.w;
            }
            #pragma unroll
            for (int c = 64; c < 67; c++) {
                float w = wr[c];
                a0 += w * p0[c];
                a1 += w * p1[c];
            }
            q_s[(2 * qp2) * 64 + qo] = a0;
            q_s[(2 * qp2 + 1) * 64 + qo] = a1;
        }
        __syncthreads();

        // qhW[h][c] = (1/sqrt(8)) * sum_d q[h*8+d] * Wk[h*8+d][c]
        {
            int h = ln & 7, c0 = ln >> 3;
            const float* qp = q_s + pt * 64 + h * 8;
            float4 qa = *(const float4*)qp;
            float4 qb = *(const float4*)(qp + 4);
            float* dst = qhW_s + pt * 544 + h * 68;
            for (int c = c0; c < 67; c += 4) {
                const float* wp = WkT_s + c * 68 + h * 8;
                float4 wa = *(const float4*)wp;
                float4 wb = *(const float4*)(wp + 4);
                float a = qa.x * wa.x + qa.y * wa.y + qa.z * wa.z + qa.w * wa.w
                        + qb.x * wb.x + qb.y * wb.y + qb.z * wb.z + qb.w * wb.w;
                dst[c] = a * 0.35355339059327373f;   // 1/sqrt(D)
            }
        }
        __syncwarp();

        int n = n0 + pt;

        // load neighbor block: 8 rows (c) x 4 cols (kk) per lane
        float4 nbv[8];
        {
            const float* nbase = neighbors + ((b * 64) * NN + n) * 16 + kq * 4;
            #pragma unroll
            for (int j = 0; j < 8; j++)
                nbv[j] = *(const float4*)(nbase + (g * 8 + j) * (NN * 16));
        }
        // gathered xyz: only lanes 0-3 (g==0) consume it
        float4 xr0 = make_float4(0.f, 0.f, 0.f, 0.f), xr1 = xr0, xr2 = xr0;
        if (ln < 4) {
            const int4 iv = *(const int4*)(idx_all + (b * NN + n) * 16 + ln * 4);
            const float* xb = xyz + b * 3 * NN;
            xr0 = make_float4(xb[iv.x], xb[iv.y], xb[iv.z], xb[iv.w]);
            xr1 = make_float4(xb[NN + iv.x], xb[NN + iv.y], xb[NN + iv.z], xb[NN + iv.w]);
            xr2 = make_float4(xb[2 * NN + iv.x], xb[2 * NN + iv.y], xb[2 * NN + iv.z], xb[2 * NN + iv.w]);
        }

        const float* qhWp = qhW_s + pt * 544;
        #pragma unroll 1
        for (int h = 0; h < 8; h++) {
            const float* qp = qhWp + h * 68;
            float4 qa = *(const float4*)(qp + g * 8);
            float4 qb = *(const float4*)(qp + g * 8 + 4);
            // energy partials over this lane's 8 channels
            float4 e = make_float4(0.f, 0.f, 0.f, 0.f);
            float qs[8] = {qa.x, qa.y, qa.z, qa.w, qb.x, qb.y, qb.z, qb.w};
            #pragma unroll
            for (int j = 0; j < 8; j++) {
                e.x += qs[j] * nbv[j].x; e.y += qs[j] * nbv[j].y;
                e.z += qs[j] * nbv[j].z; e.w += qs[j] * nbv[j].w;
            }
            if (g == 0) {   // xyz channels 64..66 counted once
                float4 qc = *(const float4*)(qp + 64);
                e.x += qc.x * xr0.x + qc.y * xr1.x + qc.z * xr2.x;
                e.y += qc.x * xr0.y + qc.y * xr1.y + qc.z * xr2.y;
                e.z += qc.x * xr0.z + qc.y * xr1.z + qc.z * xr2.z;
                e.w += qc.x * xr0.w + qc.y * xr1.w + qc.z * xr2.w;
            }
            // reduce over g (xor 4,8,16)
            #pragma unroll
            for (int m = 4; m <= 16; m <<= 1) {
                e.x += __shfl_xor_sync(0xffffffffu, e.x, m);
                e.y += __shfl_xor_sync(0xffffffffu, e.y, m);
                e.z += __shfl_xor_sync(0xffffffffu, e.z, m);
                e.w += __shfl_xor_sync(0xffffffffu, e.w, m);
            }
            // softmax over the 16 kk, no max-subtraction (|e| bounded ~4)
            float4 pr;
            pr.x = __expf(e.x); pr.y = __expf(e.y);
            pr.z = __expf(e.z); pr.w = __expf(e.w);
            float s = pr.x + pr.y + pr.z + pr.w;
            s += __shfl_xor_sync(0xffffffffu, s, 1);
            s += __shfl_xor_sync(0xffffffffu, s, 2);
            float inv = __fdividef(1.0f, s);   // applied at output (linear)

            // sp[j] partials (dot of unnormalized attn with this lane's 4 kk), j = c - g*8
            float sp[8];
            #pragma unroll
            for (int j = 0; j < 8; j++)
                sp[j] = pr.x * nbv[j].x + pr.y * nbv[j].y + pr.z * nbv[j].z + pr.w * nbv[j].w;

            // recursive-halving reduce sp over kq (xor 1, 2): 6 shfl, results distributed.
            // After: lane holds s[c0], s[c0+1] with c0 = g*8 + 4*b1l + 2*b0l
            float m0, m1;
            {
                // r1 (xor 1): keep j with ((j>>1)&1)==b0l
                int kb = 2 * b0l, sb = 2 * (1 - b0l);
                float k0 = sp[kb],     k1 = sp[kb + 1];
                float k2 = sp[4 + kb], k3 = sp[4 + kb + 1];
                k0 += __shfl_xor_sync(0xffffffffu, sp[sb],         1);
                k1 += __shfl_xor_sync(0xffffffffu, sp[sb + 1],     1);
                k2 += __shfl_xor_sync(0xffffffffu, sp[4 + sb],     1);
                k3 += __shfl_xor_sync(0xffffffffu, sp[4 + sb + 1], 1);
                // r2 (xor 2): keep j with ((j>>2)&1)==b1l
                float s0 = b1l ? k0 : k2;
                float s1 = b1l ? k1 : k3;
                m0 = b1l ? k2 : k0;
                m1 = b1l ? k3 : k1;
                m0 += __shfl_xor_sync(0xffffffffu, s0, 2);
                m1 += __shfl_xor_sync(0xffffffffu, s1, 2);
            }

            // t[oo] for all 8 outputs of this head from the lane's 2 s values
            int c0 = g * 8 + 4 * b1l + 2 * b0l;
            const float* w0 = WvT_s + c0 * 68 + h * 8;
            const float* w1 = w0 + 68;
            float4 wa0 = *(const float4*)w0, wb0 = *(const float4*)(w0 + 4);
            float4 wa1 = *(const float4*)w1, wb1 = *(const float4*)(w1 + 4);
            float tt[8];
            tt[0] = wa0.x * m0 + wa1.x * m1; tt[1] = wa0.y * m0 + wa1.y * m1;
            tt[2] = wa0.z * m0 + wa1.z * m1; tt[3] = wa0.w * m0 + wa1.w * m1;
            tt[4] = wb0.x * m0 + wb1.x * m1; tt[5] = wb0.y * m0 + wb1.y * m1;
            tt[6] = wb0.z * m0 + wb1.z * m1; tt[7] = wb0.w * m0 + wb1.w * m1;
            if (g == 0) {
                // xyz channels: in-lane kq-partial sx folded directly (butterfly sums kq)
                float sxp0 = pr.x * xr0.x + pr.y * xr0.y + pr.z * xr0.z + pr.w * xr0.w;
                float sxp1 = pr.x * xr1.x + pr.y * xr1.y + pr.z * xr1.z + pr.w * xr1.w;
                float sxp2 = pr.x * xr2.x + pr.y * xr2.y + pr.z * xr2.z + pr.w * xr2.w;
                float sxp[3] = {sxp0, sxp1, sxp2};
                #pragma unroll
                for (int j = 0; j < 3; j++) {
                    const float* wx = WvT_s + (64 + j) * 68 + h * 8;
                    float4 xa = *(const float4*)wx, xb4 = *(const float4*)(wx + 4);
                    tt[0] += xa.x * sxp[j]; tt[1] += xa.y * sxp[j];
                    tt[2] += xa.z * sxp[j]; tt[3] += xa.w * sxp[j];
                    tt[4] += xb4.x * sxp[j]; tt[5] += xb4.y * sxp[j];
                    tt[6] += xb4.z * sxp[j]; tt[7] += xb4.w * sxp[j];
                }
            }

            // recursive-halving butterfly of t[8] over all 32 lanes: 9 shfl.
            // r1 (xor 1): keep oo with (oo&1)==b0l
            float u0 = tt[b0l],     u1 = tt[2 + b0l];
            float u2 = tt[4 + b0l], u3 = tt[6 + b0l];
            u0 += __shfl_xor_sync(0xffffffffu, tt[1 - b0l], 1);
            u1 += __shfl_xor_sync(0xffffffffu, tt[3 - b0l], 1);
            u2 += __shfl_xor_sync(0xffffffffu, tt[5 - b0l], 1);
            u3 += __shfl_xor_sync(0xffffffffu, tt[7 - b0l], 1);
            // r2 (xor 2): keep oo with ((oo>>1)&1)==b1l; remaining oo = {b0l, 2+b0l, 4+b0l, 6+b0l}
            float v0 = b1l ? u1 : u0;        // oo = b0l + 2*b1l
            float v1 = b1l ? u3 : u2;        // oo = 4 + b0l + 2*b1l
            float sv0 = b1l ? u0 : u1;
            float sv1 = b1l ? u2 : u3;
            v0 += __shfl_xor_sync(0xffffffffu, sv0, 2);
            v1 += __shfl_xor_sync(0xffffffffu, sv1, 2);
            // r3 (xor 4): keep oo with ((oo>>2)&1)==b2l
            float w = b2l ? v1 : v0;         // oo = (ln & 7)
            float sw = b2l ? v0 : v1;
            w += __shfl_xor_sync(0xffffffffu, sw, 4);
            // r4, r5: full exchange over remaining g bits
            w += __shfl_xor_sync(0xffffffffu, w, 8);
            w += __shfl_xor_sync(0xffffffffu, w, 16);
            // lane ln holds out[oo = ln&7] summed over all 32 lanes (4 copies)
            if (ln < 8) out_s[pt * 64 + h * 8 + ln] = w * inv;
        }
        __syncthreads();
        // coalesced output: out[b][o][n]
        for (int idx = t; idx < 512; idx += 256) {
            int o = idx >> 3, lpt = idx & 7;
            out[(b * 64 + o) * NN + n0 + lpt] = out_s[lpt * 64 + o];
        }
        // no trailing barrier: next iteration's leading barriers order out_s reuse
    }
}

extern "C" void kernel_launch(void* const* d_in, const int* in_sizes, int n_in,
                              void* d_out, int out_size) {
    const float* pcd       = (const float*)d_in[0];
    const float* neighbors = (const float*)d_in[1];
    const float* xyz       = (const float*)d_in[2];
    const float* Wq        = (const float*)d_in[3];
    const float* Wk        = (const float*)d_in[4];
    const float* Wv        = (const float*)d_in[5];
    const int*   idx_all   = (const int*)d_in[6];
    float* out = (float*)d_out;

    // floats: WkT 4556 + WvT 4556 + Wq 4352 + qhW 4352 + q 512 + out 512 + pcd 544
    const int smem = (67 * 68 + 67 * 68 + 64 * 68 + 8 * 544 + 512 + 512 + 544) * 4;
    cudaFuncSetAttribute(attn_kernel, cudaFuncAttributeMaxDynamicSharedMemorySize, smem);
    attn_kernel<<<304, 256, smem>>>(pcd, neighbors, xyz, Wq, Wk, Wv, idx_all, out);
}

// round 16
// speedup vs baseline: 1.1623x; 1.1623x over previous
#include <cuda_runtime.h>

#define BB 4
#define NN 16384
#define CC 64
#define KI 16
#define HH 8

// ---------------- fused kernel: q-projection + gather + factored attention ----------------
// warp per point; lane = 4*g + kq; lane holds nb[c=8g..8g+7][kk=4kq..4kq+3]
__global__ __launch_bounds__(256, 2) void attn_kernel(
    const float* __restrict__ pcd, const float* __restrict__ neighbors,
    const float* __restrict__ xyz,
    const float* __restrict__ Wq, const float* __restrict__ Wk,
    const float* __restrict__ Wv,
    const int* __restrict__ idx_all, float* __restrict__ out)
{
    extern __shared__ float sm[];
    float* WkT_s = sm;                    // [c][o], 67*68
    float* WvT_s = WkT_s + 67 * 68;       // [c][o] transposed, 67*68
    float* Wq_s  = WvT_s + 67 * 68;       // [o][c] row-major, 64*68
    float* qhW_s = Wq_s + 64 * 68;        // [pt][h*68 + c], 8*544
    float* q_s   = qhW_s + 8 * 544;       // [pt][o], 512
    float* out_s = q_s + 512;             // [pt][o], 512
    float* pcd_s = out_s + 512;           // [nn][c] transposed, 8*68

    int t = threadIdx.x;
    for (int idx = t; idx < 64 * 67; idx += 256) {
        int o = idx / 67, c = idx % 67;
        WkT_s[c * 68 + o] = Wk[idx];
        WvT_s[c * 68 + o] = Wv[idx];
        Wq_s[o * 68 + c] = Wq[idx];
    }
    __syncthreads();

    const int pt = t >> 5, ln = t & 31, g = ln >> 2, kq = ln & 3;
    const int b0l = ln & 1, b1l = (ln >> 1) & 1, b2l = (ln >> 2) & 1;
    const int qo = t & 63, qp2 = t >> 6;          // q-projection mapping
    const int NTILE = (BB * NN) / 8;              // 8192

    for (int tile = blockIdx.x; tile < NTILE; tile += gridDim.x) {
        int b = (tile * 8) >> 14;
        int n0 = (tile * 8) & (NN - 1);

        // stage pcd_cat tile transposed: pcd_s[nn*68 + c]
        for (int idx = t; idx < 536; idx += 256) {
            int c = idx >> 3, nn = idx & 7;
            float v = (c < 64) ? pcd[(b * 64 + c) * NN + n0 + nn]
                               : xyz[(b * 3 + (c - 64)) * NN + n0 + nn];
            pcd_s[nn * 68 + c] = v;
        }
        __syncthreads();

        // q[pt][o] = sum_c Wq[o,c] * pcd_cat[c, n0+pt]; each thread does 2 pts
        {
            float a0 = 0.f, a1 = 0.f;
            const float* wr = Wq_s + qo * 68;
            const float* p0 = pcd_s + (2 * qp2) * 68;
            const float* p1 = p0 + 68;
            #pragma unroll
            for (int k4 = 0; k4 < 16; k4++) {
                float4 w = *(const float4*)(wr + 4 * k4);
                float4 x0 = *(const float4*)(p0 + 4 * k4);
                float4 x1 = *(const float4*)(p1 + 4 * k4);
                a0 += w.x * x0.x + w.y * x0.y + w.z * x0.z + w.w * x0.w;
                a1 += w.x * x1.x + w.y * x1.y + w.z * x1.z + w.w * x1.w;
            }
            #pragma unroll
            for (int c = 64; c < 67; c++) {
                float w = wr[c];
                a0 += w * p0[c];
                a1 += w * p1[c];
            }
            q_s[(2 * qp2) * 64 + qo] = a0;
            q_s[(2 * qp2 + 1) * 64 + qo] = a1;
        }
        __syncthreads();

        // qhW[h][c] = (1/sqrt(8)) * sum_d q[h*8+d] * Wk[h*8+d][c]
        {
            int h = ln & 7, c0i = ln >> 3;
            const float* qp = q_s + pt * 64 + h * 8;
            float4 qa = *(const float4*)qp;
            float4 qb = *(const float4*)(qp + 4);
            float* dst = qhW_s + pt * 544 + h * 68;
            for (int c = c0i; c < 67; c += 4) {
                const float* wp = WkT_s + c * 68 + h * 8;
                float4 wa = *(const float4*)wp;
                float4 wb = *(const float4*)(wp + 4);
                float a = qa.x * wa.x + qa.y * wa.y + qa.z * wa.z + qa.w * wa.w
                        + qb.x * wb.x + qb.y * wb.y + qb.z * wb.z + qb.w * wb.w;
                dst[c] = a * 0.35355339059327373f;   // 1/sqrt(D)
            }
        }
        __syncwarp();

        int n = n0 + pt;

        // load neighbor block: 8 rows (c) x 4 cols (kk) per lane
        float4 nbv[8];
        {
            const float* nbase = neighbors + ((b * 64) * NN + n) * 16 + kq * 4;
            #pragma unroll
            for (int j = 0; j < 8; j++)
                nbv[j] = *(const float4*)(nbase + (g * 8 + j) * (NN * 16));
        }
        // gathered xyz: only lanes 0-3 (g==0) consume it
        float4 xr0 = make_float4(0.f, 0.f, 0.f, 0.f), xr1 = xr0, xr2 = xr0;
        if (ln < 4) {
            const int4 iv = *(const int4*)(idx_all + (b * NN + n) * 16 + ln * 4);
            const float* xb = xyz + b * 3 * NN;
            xr0 = make_float4(xb[iv.x], xb[iv.y], xb[iv.z], xb[iv.w]);
            xr1 = make_float4(xb[NN + iv.x], xb[NN + iv.y], xb[NN + iv.z], xb[NN + iv.w]);
            xr2 = make_float4(xb[2 * NN + iv.x], xb[2 * NN + iv.y], xb[2 * NN + iv.z], xb[2 * NN + iv.w]);
        }

        const float* qhWp = qhW_s + pt * 544;
        #pragma unroll 1
        for (int h = 0; h < 8; h++) {
            const float* qp = qhWp + h * 68;
            float4 qa = *(const float4*)(qp + g * 8);
            float4 qb = *(const float4*)(qp + g * 8 + 4);
            // energy partials over this lane's 8 channels
            float4 e = make_float4(0.f, 0.f, 0.f, 0.f);
            float qs[8] = {qa.x, qa.y, qa.z, qa.w, qb.x, qb.y, qb.z, qb.w};
            #pragma unroll
            for (int j = 0; j < 8; j++) {
                e.x += qs[j] * nbv[j].x; e.y += qs[j] * nbv[j].y;
                e.z += qs[j] * nbv[j].z; e.w += qs[j] * nbv[j].w;
            }
            if (g == 0) {   // xyz channels 64..66 counted once
                float4 qc = *(const float4*)(qp + 64);
                e.x += qc.x * xr0.x + qc.y * xr1.x + qc.z * xr2.x;
                e.y += qc.x * xr0.y + qc.y * xr1.y + qc.z * xr2.y;
                e.z += qc.x * xr0.z + qc.y * xr1.z + qc.z * xr2.z;
                e.w += qc.x * xr0.w + qc.y * xr1.w + qc.z * xr2.w;
            }
            // reduce over g (xor 4,8,16)
            #pragma unroll
            for (int m = 4; m <= 16; m <<= 1) {
                e.x += __shfl_xor_sync(0xffffffffu, e.x, m);
                e.y += __shfl_xor_sync(0xffffffffu, e.y, m);
                e.z += __shfl_xor_sync(0xffffffffu, e.z, m);
                e.w += __shfl_xor_sync(0xffffffffu, e.w, m);
            }
            // softmax over the 16 kk, no max-subtraction (|e| bounded ~4)
            float4 pr;
            pr.x = __expf(e.x); pr.y = __expf(e.y);
            pr.z = __expf(e.z); pr.w = __expf(e.w);
            float s = pr.x + pr.y + pr.z + pr.w;
            s += __shfl_xor_sync(0xffffffffu, s, 1);
            s += __shfl_xor_sync(0xffffffffu, s, 2);
            float inv = __fdividef(1.0f, s);   // applied at output (linear)

            // sp partials (dot of unnormalized attn with this lane's 4 kk) — NAMED scalars
            float sp0 = pr.x * nbv[0].x + pr.y * nbv[0].y + pr.z * nbv[0].z + pr.w * nbv[0].w;
            float sp1 = pr.x * nbv[1].x + pr.y * nbv[1].y + pr.z * nbv[1].z + pr.w * nbv[1].w;
            float sp2 = pr.x * nbv[2].x + pr.y * nbv[2].y + pr.z * nbv[2].z + pr.w * nbv[2].w;
            float sp3 = pr.x * nbv[3].x + pr.y * nbv[3].y + pr.z * nbv[3].z + pr.w * nbv[3].w;
            float sp4 = pr.x * nbv[4].x + pr.y * nbv[4].y + pr.z * nbv[4].z + pr.w * nbv[4].w;
            float sp5 = pr.x * nbv[5].x + pr.y * nbv[5].y + pr.z * nbv[5].z + pr.w * nbv[5].w;
            float sp6 = pr.x * nbv[6].x + pr.y * nbv[6].y + pr.z * nbv[6].z + pr.w * nbv[6].w;
            float sp7 = pr.x * nbv[7].x + pr.y * nbv[7].y + pr.z * nbv[7].z + pr.w * nbv[7].w;

            // recursive-halving reduce sp over kq (xor 1, 2): 6 shfl, ternary SELs only.
            // After: lane holds s[c0], s[c0+1] with c0 = g*8 + 4*b1l + 2*b0l
            float m0, m1;
            {
                // r1 (xor 1): keep j-pair with ((j>>1)&1)==b0l
                float kk0 = b0l ? sp2 : sp0, sd0 = b0l ? sp0 : sp2;
                float kk1 = b0l ? sp3 : sp1, sd1 = b0l ? sp1 : sp3;
                float kk2 = b0l ? sp6 : sp4, sd2 = b0l ? sp4 : sp6;
                float kk3 = b0l ? sp7 : sp5, sd3 = b0l ? sp5 : sp7;
                kk0 += __shfl_xor_sync(0xffffffffu, sd0, 1);
                kk1 += __shfl_xor_sync(0xffffffffu, sd1, 1);
                kk2 += __shfl_xor_sync(0xffffffffu, sd2, 1);
                kk3 += __shfl_xor_sync(0xffffffffu, sd3, 1);
                // r2 (xor 2): keep half with ((j>>2)&1)==b1l
                float s0 = b1l ? kk0 : kk2;
                float s1 = b1l ? kk1 : kk3;
                m0 = b1l ? kk2 : kk0;
                m1 = b1l ? kk3 : kk1;
                m0 += __shfl_xor_sync(0xffffffffu, s0, 2);
                m1 += __shfl_xor_sync(0xffffffffu, s1, 2);
            }

            // t[oo] for all 8 outputs of this head from the lane's 2 s values — NAMED
            int c0 = g * 8 + 4 * b1l + 2 * b0l;
            const float* w0 = WvT_s + c0 * 68 + h * 8;
            const float* w1 = w0 + 68;
            float4 wa0 = *(const float4*)w0, wb0 = *(const float4*)(w0 + 4);
            float4 wa1 = *(const float4*)w1, wb1 = *(const float4*)(w1 + 4);
            float tt0 = wa0.x * m0 + wa1.x * m1, tt1 = wa0.y * m0 + wa1.y * m1;
            float tt2 = wa0.z * m0 + wa1.z * m1, tt3 = wa0.w * m0 + wa1.w * m1;
            float tt4 = wb0.x * m0 + wb1.x * m1, tt5 = wb0.y * m0 + wb1.y * m1;
            float tt6 = wb0.z * m0 + wb1.z * m1, tt7 = wb0.w * m0 + wb1.w * m1;
            if (g == 0) {
                // xyz channels: in-lane kq-partial sx folded directly (butterfly sums kq)
                float sxp0 = pr.x * xr0.x + pr.y * xr0.y + pr.z * xr0.z + pr.w * xr0.w;
                float sxp1 = pr.x * xr1.x + pr.y * xr1.y + pr.z * xr1.z + pr.w * xr1.w;
                float sxp2 = pr.x * xr2.x + pr.y * xr2.y + pr.z * xr2.z + pr.w * xr2.w;
                const float* wx0 = WvT_s + 64 * 68 + h * 8;
                const float* wx1 = WvT_s + 65 * 68 + h * 8;
                const float* wx2 = WvT_s + 66 * 68 + h * 8;
                float4 xa0 = *(const float4*)wx0, xb0 = *(const float4*)(wx0 + 4);
                float4 xa1 = *(const float4*)wx1, xb1 = *(const float4*)(wx1 + 4);
                float4 xa2 = *(const float4*)wx2, xb2 = *(const float4*)(wx2 + 4);
                tt0 += xa0.x * sxp0 + xa1.x * sxp1 + xa2.x * sxp2;
                tt1 += xa0.y * sxp0 + xa1.y * sxp1 + xa2.y * sxp2;
                tt2 += xa0.z * sxp0 + xa1.z * sxp1 + xa2.z * sxp2;
                tt3 += xa0.w * sxp0 + xa1.w * sxp1 + xa2.w * sxp2;
                tt4 += xb0.x * sxp0 + xb1.x * sxp1 + xb2.x * sxp2;
                tt5 += xb0.y * sxp0 + xb1.y * sxp1 + xb2.y * sxp2;
                tt6 += xb0.z * sxp0 + xb1.z * sxp1 + xb2.z * sxp2;
                tt7 += xb0.w * sxp0 + xb1.w * sxp1 + xb2.w * sxp2;
            }

            // recursive-halving butterfly of tt over all 32 lanes: 9 shfl, ternary SELs.
            // r1 (xor 1): keep oo with (oo&1)==b0l
            float u0 = (b0l ? tt1 : tt0) ;
            float su0 = (b0l ? tt0 : tt1);
            float u1 = (b0l ? tt3 : tt2);
            float su1 = (b0l ? tt2 : tt3);
            float u2 = (b0l ? tt5 : tt4);
            float su2 = (b0l ? tt4 : tt5);
            float u3 = (b0l ? tt7 : tt6);
            float su3 = (b0l ? tt6 : tt7);
            u0 += __shfl_xor_sync(0xffffffffu, su0, 1);
            u1 += __shfl_xor_sync(0xffffffffu, su1, 1);
            u2 += __shfl_xor_sync(0xffffffffu, su2, 1);
            u3 += __shfl_xor_sync(0xffffffffu, su3, 1);
            // r2 (xor 2): keep oo with ((oo>>1)&1)==b1l
            float v0 = b1l ? u1 : u0;        // oo = b0l + 2*b1l
            float v1 = b1l ? u3 : u2;        // oo = 4 + b0l + 2*b1l
            float sv0 = b1l ? u0 : u1;
            float sv1 = b1l ? u2 : u3;
            v0 += __shfl_xor_sync(0xffffffffu, sv0, 2);
            v1 += __shfl_xor_sync(0xffffffffu, sv1, 2);
            // r3 (xor 4): keep oo with ((oo>>2)&1)==b2l
            float w = b2l ? v1 : v0;         // oo = (ln & 7)
            float sw = b2l ? v0 : v1;
            w += __shfl_xor_sync(0xffffffffu, sw, 4);
            // r4, r5: full exchange over remaining g bits
            w += __shfl_xor_sync(0xffffffffu, w, 8);
            w += __shfl_xor_sync(0xffffffffu, w, 16);
            // lane ln holds out[oo = ln&7] summed over all 32 lanes (4 copies)
            if (ln < 8) out_s[pt * 64 + h * 8 + ln] = w * inv;
        }
        __syncthreads();
        // coalesced output: out[b][o][n]
        for (int idx = t; idx < 512; idx += 256) {
            int o = idx >> 3, lpt = idx & 7;
            out[(b * 64 + o) * NN + n0 + lpt] = out_s[lpt * 64 + o];
        }
        // no trailing barrier: next iteration's leading barriers order out_s reuse
    }
}

extern "C" void kernel_launch(void* const* d_in, const int* in_sizes, int n_in,
                              void* d_out, int out_size) {
    const float* pcd       = (const float*)d_in[0];
    const float* neighbors = (const float*)d_in[1];
    const float* xyz       = (const float*)d_in[2];
    const float* Wq        = (const float*)d_in[3];
    const float* Wk        = (const float*)d_in[4];
    const float* Wv        = (const float*)d_in[5];
    const int*   idx_all   = (const int*)d_in[6];
    float* out = (float*)d_out;

    // floats: WkT 4556 + WvT 4556 + Wq 4352 + qhW 4352 + q 512 + out 512 + pcd 544
    const int smem = (67 * 68 + 67 * 68 + 64 * 68 + 8 * 544 + 512 + 512 + 544) * 4;
    cudaFuncSetAttribute(attn_kernel, cudaFuncAttributeMaxDynamicSharedMemorySize, smem);
    attn_kernel<<<304, 256, smem>>>(pcd, neighbors, xyz, Wq, Wk, Wv, idx_all, out);
}